// round 2
// baseline (speedup 1.0000x reference)
#include <cuda_runtime.h>
#include <cuda_fp16.h>
#include <cuda_bf16.h>

#define SEQ   2048
#define DIN   1024
#define DHID  2048
#define DOUT  512
#define NPROJ 8192   // 4 gates * DHID

// ---- recurrent kernel geometry ----
#define NJ       14            // hidden units per CTA
#define RWARPS   14            // one warp per hidden unit
#define RTHREADS (RWARPS * 32) // 448
#define RGRID    147           // ceil(2048 / 14), <= 148 SMs -> all co-resident
#define SMEM_REC (NJ * 4 * DHID * 2)  // 229376 B of bf16 weights

// ---- device scratch (allocation-free requirement) ----
__device__ float          g_xproj[(size_t)SEQ * NPROJ];   // 64 MB: [t][g*2048+j]
__device__ __nv_bfloat16  g_wh[(size_t)4 * DHID * DHID];  // 32 MB: [(g*2048+j)*2048+k]
__device__ float          g_h[2][DHID];                   // double-buffered hidden state
__device__ unsigned       g_flag[160];                    // per-CTA step flags (+sentinels)

struct Ptrs { const float* W[4]; const float* b[4]; };

// ---- strong-relaxed global ops + fences (no atomics, no CCTL.IVALL) ----
__device__ __forceinline__ unsigned ld_flag(const unsigned* p) {
    unsigned v;
    asm volatile("ld.relaxed.gpu.u32 %0, [%1];" : "=r"(v) : "l"(p) : "memory");
    return v;
}
__device__ __forceinline__ void st_flag(unsigned* p, unsigned v) {
    asm volatile("st.relaxed.gpu.u32 [%0], %1;" :: "l"(p), "r"(v) : "memory");
}
__device__ __forceinline__ void fence_gpu() {
    asm volatile("fence.acq_rel.gpu;" ::: "memory");
}

// ---------------------------------------------------------------------------
// init: zero h, init flags (runs every launch -> graph-replay safe)
// ---------------------------------------------------------------------------
__global__ void k_init() {
    int i = blockIdx.x * blockDim.x + threadIdx.x;
    if (i < 2 * DHID) ((float*)g_h)[i] = 0.0f;
    if (i < 160) g_flag[i] = (i < RGRID) ? 0u : 0xFFFFFFFFu;  // sentinels always pass
}

// ---------------------------------------------------------------------------
// pack: transpose h-part of each gate weight [3072,2048] -> bf16 [g][j][k]
// ---------------------------------------------------------------------------
__global__ void k_pack(Ptrs p) {
    __shared__ float tile[32][33];
    int g  = blockIdx.z;
    int k0 = blockIdx.x * 32;
    int j0 = blockIdx.y * 32;
    tile[threadIdx.y][threadIdx.x] =
        p.W[g][(size_t)(DIN + k0 + threadIdx.y) * DHID + j0 + threadIdx.x];
    __syncthreads();
    g_wh[((size_t)g * DHID + j0 + threadIdx.y) * DHID + k0 + threadIdx.x] =
        __float2bfloat16(tile[threadIdx.x][threadIdx.y]);
}

// ---------------------------------------------------------------------------
// xproj GEMM: g_xproj[t][g*2048+j] = b_g[j] + sum_k x[t,k] * W_g[k,j]
// 128x128 tile, BK=8, 256 threads, 8x8 microtile, fp32.
// ---------------------------------------------------------------------------
__global__ __launch_bounds__(256, 2) void k_xproj(const float* __restrict__ x, Ptrs p) {
    __shared__ float As[8][128];   // [k][m]
    __shared__ float Bs[8][128];   // [k][n]
    int n0 = blockIdx.x * 128;
    int m0 = blockIdx.y * 128;
    int g  = n0 >> 11;                 // gate constant per CTA (2048 | 128-tile grid)
    int jb = n0 & (DHID - 1);
    const float* __restrict__ W = p.W[g];
    int tid  = threadIdx.x;
    int arow = tid >> 1, akq = (tid & 1) << 2;      // A loader: 128 rows x 8 k
    int brow = tid >> 5, bcol = (tid & 31) << 2;    // B loader: 8 rows x 128 n
    int tm = (tid >> 4) << 3;
    int tn = (tid & 15) << 3;
    float acc[8][8] = {};

    for (int k0 = 0; k0 < DIN; k0 += 8) {
        float4 av = *(const float4*)&x[(size_t)(m0 + arow) * DIN + k0 + akq];
        float4 bv = *(const float4*)&W[(size_t)(k0 + brow) * DHID + jb + bcol];
        __syncthreads();
        As[akq + 0][arow] = av.x;
        As[akq + 1][arow] = av.y;
        As[akq + 2][arow] = av.z;
        As[akq + 3][arow] = av.w;
        *(float4*)&Bs[brow][bcol] = bv;
        __syncthreads();
#pragma unroll
        for (int kk = 0; kk < 8; kk++) {
            float4 a0 = *(const float4*)&As[kk][tm];
            float4 a1 = *(const float4*)&As[kk][tm + 4];
            float4 b0 = *(const float4*)&Bs[kk][tn];
            float4 b1 = *(const float4*)&Bs[kk][tn + 4];
            float am[8] = {a0.x, a0.y, a0.z, a0.w, a1.x, a1.y, a1.z, a1.w};
            float bn[8] = {b0.x, b0.y, b0.z, b0.w, b1.x, b1.y, b1.z, b1.w};
#pragma unroll
            for (int mm = 0; mm < 8; mm++)
#pragma unroll
                for (int nn = 0; nn < 8; nn++)
                    acc[mm][nn] += am[mm] * bn[nn];
        }
    }

    const float* bg = p.b[g];
#pragma unroll
    for (int mm = 0; mm < 8; mm++) {
        int m = m0 + tm + mm;
#pragma unroll
        for (int nn = 0; nn < 8; nn += 4) {
            float4 o;
            o.x = acc[mm][nn + 0] + bg[jb + tn + nn + 0];
            o.y = acc[mm][nn + 1] + bg[jb + tn + nn + 1];
            o.z = acc[mm][nn + 2] + bg[jb + tn + nn + 2];
            o.w = acc[mm][nn + 3] + bg[jb + tn + nn + 3];
            *(float4*)&g_xproj[(size_t)m * NPROJ + n0 + tn + nn] = o;
        }
    }
}

// ---------------------------------------------------------------------------
// recurrent persistent kernel
// ---------------------------------------------------------------------------
__device__ __forceinline__ float sigm_(float v) { return 1.0f / (1.0f + __expf(-v)); }
__device__ __forceinline__ float tanh_(float v) { return 2.0f / (1.0f + __expf(-2.0f * v)) - 1.0f; }

// bf16 pair (packed in u32) -> two f32 via pure ALU ops (alu pipe, dual-issues vs FFMA)
#define BF2LO(u) __int_as_float((u) << 16)
#define BF2HI(u) __int_as_float((u) & 0xffff0000u)

__global__ void __launch_bounds__(RTHREADS, 1) k_rec() {
    extern __shared__ __nv_bfloat16 sw[];   // [(jl*4+g)*2048 + k]
    int tid  = threadIdx.x;
    int w    = tid >> 5;
    int lane = tid & 31;
    int j0   = blockIdx.x * NJ;
    int nj   = DHID - j0; if (nj > NJ) nj = NJ;

    // ---- stage this CTA's bf16 weight slice into smem (one time) ----
    {
        int nvec = nj * 4 * (DHID / 8);            // uint4 = 8 bf16, 256 per row
        uint4* dst = (uint4*)sw;
        for (int t = tid; t < nvec; t += RTHREADS) {
            int r  = t >> 8;                        // smem row = jl*4+g
            int c  = t & 255;
            int jl = r >> 2, g = r & 3;
            const uint4* src = (const uint4*)(g_wh + ((size_t)g * DHID + j0 + jl) * DHID);
            dst[(r << 8) + c] = src[c];
        }
    }
    __syncthreads();

    bool active = (w < nj);
    int  jg     = j0 + w;
    const __nv_bfloat16* wrow = sw + (size_t)(w * 4) * DHID;
    float cst = 0.0f;

#pragma unroll 1
    for (int s = 0; s < SEQ; ++s) {
        const float* hprev = g_h[s & 1];
        float*       hnext = g_h[(s + 1) & 1];

        if (active) {
            const float* xp = g_xproj + (size_t)s * NPROJ + jg;
            float x0 = __ldcg(xp);
            float x1 = __ldcg(xp + DHID);
            float x2 = __ldcg(xp + 2 * DHID);
            float x3 = __ldcg(xp + 3 * DHID);

            float a0 = 0.f, a1 = 0.f, a2 = 0.f, a3 = 0.f;
#pragma unroll
            for (int i = 0; i < 8; i++) {
                int k0 = (i << 8) + (lane << 3);    // 8 k per lane per iter
                float4 h0 = __ldcg((const float4*)(hprev + k0));
                float4 h1 = __ldcg((const float4*)(hprev + k0 + 4));
#define GATE(acc, goff)                                                       \
                {                                                             \
                    uint4 wv = *(const uint4*)(wrow + (goff) + k0);           \
                    acc += BF2LO(wv.x) * h0.x + BF2HI(wv.x) * h0.y;           \
                    acc += BF2LO(wv.y) * h0.z + BF2HI(wv.y) * h0.w;           \
                    acc += BF2LO(wv.z) * h1.x + BF2HI(wv.z) * h1.y;           \
                    acc += BF2LO(wv.w) * h1.z + BF2HI(wv.w) * h1.w;           \
                }
                GATE(a0, 0)
                GATE(a1, DHID)
                GATE(a2, 2 * DHID)
                GATE(a3, 3 * DHID)
#undef GATE
            }
#pragma unroll
            for (int off = 16; off; off >>= 1) {
                a0 += __shfl_xor_sync(0xffffffffu, a0, off);
                a1 += __shfl_xor_sync(0xffffffffu, a1, off);
                a2 += __shfl_xor_sync(0xffffffffu, a2, off);
                a3 += __shfl_xor_sync(0xffffffffu, a3, off);
            }
            float f  = sigm_(a0 + x0);
            float ig = sigm_(a1 + x1);
            float gg = tanh_(a2 + x2);
            float oo = sigm_(a3 + x3);
            cst = cst * f + ig * gg;
            float hn = tanh_(cst) * oo;
            if (lane == 0) __stcg(hnext + jg, hn);
        }

        if (s < SEQ - 1) {
            unsigned tgt = (unsigned)(s + 1);
            __syncthreads();                       // all warps done with step s
            if (tid == 0) {                        // publish: release + own flag
                fence_gpu();
                st_flag(&g_flag[blockIdx.x], tgt);
            }
            if (tid < 32) {                        // warp 0 polls all 147 flags
                for (;;) {
                    bool ok = ld_flag(&g_flag[tid])       >= tgt
                           && ld_flag(&g_flag[tid + 32])  >= tgt
                           && ld_flag(&g_flag[tid + 64])  >= tgt
                           && ld_flag(&g_flag[tid + 96])  >= tgt
                           && ld_flag(&g_flag[tid + 128]) >= tgt;
                    if (__all_sync(0xffffffffu, ok)) break;
                }
                fence_gpu();                       // acquire
            }
            __syncthreads();                       // release whole CTA into s+1
        }
    }
}

// ---------------------------------------------------------------------------
// output: out[o] = b_out[o] + sum_j h_last[j] * W_out[j,o]   (h_last = g_h[0])
// ---------------------------------------------------------------------------
__global__ __launch_bounds__(256) void k_out(const float* __restrict__ Wout,
                                             const float* __restrict__ bout,
                                             float* __restrict__ out) {
    __shared__ float red[4][64];
    int ol  = threadIdx.x & 63;
    int seg = threadIdx.x >> 6;
    int o   = blockIdx.x * 64 + ol;
    const float* h = g_h[0];      // SEQ even -> final h lands in buffer 0
    float acc = 0.0f;
    int kbeg = seg * 512;
#pragma unroll 4
    for (int k = kbeg; k < kbeg + 512; ++k)
        acc += h[k] * Wout[(size_t)k * DOUT + o];
    red[seg][ol] = acc;
    __syncthreads();
    if (seg == 0)
        out[o] = bout[o] + red[0][ol] + red[1][ol] + red[2][ol] + red[3][ol];
}

// ---------------------------------------------------------------------------
extern "C" void kernel_launch(void* const* d_in, const int* in_sizes, int n_in,
                              void* d_out, int out_size) {
    const float* x = (const float*)d_in[0];
    Ptrs p;
    p.W[0] = (const float*)d_in[1]; p.b[0] = (const float*)d_in[2];   // f
    p.W[1] = (const float*)d_in[3]; p.b[1] = (const float*)d_in[4];   // i
    p.W[2] = (const float*)d_in[5]; p.b[2] = (const float*)d_in[6];   // c (g)
    p.W[3] = (const float*)d_in[7]; p.b[3] = (const float*)d_in[8];   // o
    const float* Wout = (const float*)d_in[9];
    const float* bout = (const float*)d_in[10];

    cudaFuncSetAttribute(k_rec, cudaFuncAttributeMaxDynamicSharedMemorySize, SMEM_REC);

    k_init<<<4, 1024>>>();
    k_pack<<<dim3(DHID / 32, DHID / 32, 4), dim3(32, 32)>>>(p);
    k_xproj<<<dim3(NPROJ / 128, SEQ / 128), 256>>>(x, p);
    k_rec<<<RGRID, RTHREADS, SMEM_REC>>>();
    k_out<<<DOUT / 64, 256>>>(Wout, bout, (float*)d_out);
}

// round 3
// speedup vs baseline: 1.3990x; 1.3990x over previous
#include <cuda_runtime.h>
#include <cuda_fp16.h>
#include <cuda_bf16.h>

#define SEQ   2048
#define DIN   1024
#define DHID  2048
#define DOUT  512
#define NPROJ 8192   // 4 gates * DHID

// ---- recurrent kernel geometry ----
#define NJ       14             // hidden units per CTA (2 per warp)
#define RWARPS   7
#define RTHREADS (RWARPS * 32)  // 224
#define RGRID    147            // compute CTAs; CTA 147 = barrier aggregator
#define SMEM_REC (NJ * 4 * DHID * 2)  // 229376 B of bf16 weights

// ---- device scratch (allocation-free requirement) ----
__device__ float          g_xproj[(size_t)SEQ * NPROJ];   // 64 MB: [t][g*2048+j]
__device__ __nv_bfloat16  g_wh[(size_t)4 * DHID * DHID];  // 32 MB: [(g*2048+j)*2048+k]
__device__ float          g_h[2][DHID];                   // double-buffered hidden state
__device__ unsigned       g_flag[160];                    // per-CTA step flags (+sentinels)
__device__ unsigned       g_epoch;                        // aggregator-published epoch

struct Ptrs { const float* W[4]; const float* b[4]; };

// ---- relaxed global ops + fences (no atomics, no L1 flush) ----
__device__ __forceinline__ unsigned ld_flag(const unsigned* p) {
    unsigned v;
    asm volatile("ld.relaxed.gpu.u32 %0, [%1];" : "=r"(v) : "l"(p) : "memory");
    return v;
}
__device__ __forceinline__ void st_flag(unsigned* p, unsigned v) {
    asm volatile("st.relaxed.gpu.u32 [%0], %1;" :: "l"(p), "r"(v) : "memory");
}
__device__ __forceinline__ void fence_gpu() {
    asm volatile("fence.acq_rel.gpu;" ::: "memory");
}

// ---------------------------------------------------------------------------
// init: zero h, init flags + epoch (runs every launch -> graph-replay safe)
// ---------------------------------------------------------------------------
__global__ void k_init() {
    int i = blockIdx.x * blockDim.x + threadIdx.x;
    if (i < 2 * DHID) ((float*)g_h)[i] = 0.0f;
    if (i < 160) g_flag[i] = (i < RGRID) ? 0u : 0xFFFFFFFFu;  // sentinels always pass
    if (i == 0) g_epoch = 0u;
}

// ---------------------------------------------------------------------------
// pack: transpose h-part of each gate weight [3072,2048] -> bf16 [g][j][k]
// ---------------------------------------------------------------------------
__global__ void k_pack(Ptrs p) {
    __shared__ float tile[32][33];
    int g  = blockIdx.z;
    int k0 = blockIdx.x * 32;
    int j0 = blockIdx.y * 32;
    tile[threadIdx.y][threadIdx.x] =
        p.W[g][(size_t)(DIN + k0 + threadIdx.y) * DHID + j0 + threadIdx.x];
    __syncthreads();
    g_wh[((size_t)g * DHID + j0 + threadIdx.y) * DHID + k0 + threadIdx.x] =
        __float2bfloat16(tile[threadIdx.x][threadIdx.y]);
}

// ---------------------------------------------------------------------------
// xproj GEMM: g_xproj[t][g*2048+j] = b_g[j] + sum_k x[t,k] * W_g[k,j]
// 128x128 tile, BK=8, 256 threads, 8x8 microtile, fp32.
// ---------------------------------------------------------------------------
__global__ __launch_bounds__(256, 2) void k_xproj(const float* __restrict__ x, Ptrs p) {
    __shared__ float As[8][128];   // [k][m]
    __shared__ float Bs[8][128];   // [k][n]
    int n0 = blockIdx.x * 128;
    int m0 = blockIdx.y * 128;
    int g  = n0 >> 11;
    int jb = n0 & (DHID - 1);
    const float* __restrict__ W = p.W[g];
    int tid  = threadIdx.x;
    int arow = tid >> 1, akq = (tid & 1) << 2;
    int brow = tid >> 5, bcol = (tid & 31) << 2;
    int tm = (tid >> 4) << 3;
    int tn = (tid & 15) << 3;
    float acc[8][8] = {};

    for (int k0 = 0; k0 < DIN; k0 += 8) {
        float4 av = *(const float4*)&x[(size_t)(m0 + arow) * DIN + k0 + akq];
        float4 bv = *(const float4*)&W[(size_t)(k0 + brow) * DHID + jb + bcol];
        __syncthreads();
        As[akq + 0][arow] = av.x;
        As[akq + 1][arow] = av.y;
        As[akq + 2][arow] = av.z;
        As[akq + 3][arow] = av.w;
        *(float4*)&Bs[brow][bcol] = bv;
        __syncthreads();
#pragma unroll
        for (int kk = 0; kk < 8; kk++) {
            float4 a0 = *(const float4*)&As[kk][tm];
            float4 a1 = *(const float4*)&As[kk][tm + 4];
            float4 b0 = *(const float4*)&Bs[kk][tn];
            float4 b1 = *(const float4*)&Bs[kk][tn + 4];
            float am[8] = {a0.x, a0.y, a0.z, a0.w, a1.x, a1.y, a1.z, a1.w};
            float bn[8] = {b0.x, b0.y, b0.z, b0.w, b1.x, b1.y, b1.z, b1.w};
#pragma unroll
            for (int mm = 0; mm < 8; mm++)
#pragma unroll
                for (int nn = 0; nn < 8; nn++)
                    acc[mm][nn] += am[mm] * bn[nn];
        }
    }

    const float* bg = p.b[g];
#pragma unroll
    for (int mm = 0; mm < 8; mm++) {
        int m = m0 + tm + mm;
#pragma unroll
        for (int nn = 0; nn < 8; nn += 4) {
            float4 o;
            o.x = acc[mm][nn + 0] + bg[jb + tn + nn + 0];
            o.y = acc[mm][nn + 1] + bg[jb + tn + nn + 1];
            o.z = acc[mm][nn + 2] + bg[jb + tn + nn + 2];
            o.w = acc[mm][nn + 3] + bg[jb + tn + nn + 3];
            *(float4*)&g_xproj[(size_t)m * NPROJ + n0 + tn + nn] = o;
        }
    }
}

// ---------------------------------------------------------------------------
// recurrent persistent kernel
// ---------------------------------------------------------------------------
__device__ __forceinline__ float sigm_(float v) { return 1.0f / (1.0f + __expf(-v)); }
__device__ __forceinline__ float tanh_(float v) { return 2.0f / (1.0f + __expf(-2.0f * v)) - 1.0f; }

// bf16 pair (packed u32) -> two f32 via pure ALU ops
#define BF2LO(u) __int_as_float((u) << 16)
#define BF2HI(u) __int_as_float((u) & 0xffff0000u)

__global__ void __launch_bounds__(RTHREADS, 1) k_rec() {
    extern __shared__ __nv_bfloat16 sw[];   // [(jl*4+g)*2048 + k]
    int tid  = threadIdx.x;
    int lane = tid & 31;

    // ================= aggregator CTA: barrier service only =================
    if (blockIdx.x == RGRID) {
        if (tid < 32) {
            for (unsigned tgt = 1; tgt < SEQ; ++tgt) {
                for (;;) {
                    // 5 independent loads -> overlapped L2 latency
                    unsigned v0 = ld_flag(&g_flag[lane]);
                    unsigned v1 = ld_flag(&g_flag[lane + 32]);
                    unsigned v2 = ld_flag(&g_flag[lane + 64]);
                    unsigned v3 = ld_flag(&g_flag[lane + 96]);
                    unsigned v4 = ld_flag(&g_flag[lane + 128]);
                    unsigned mn = min(min(v0, v1), min(min(v2, v3), v4));
                    if (__all_sync(0xffffffffu, mn >= tgt)) break;
                }
                if (lane == 0) { fence_gpu(); st_flag(&g_epoch, tgt); }
            }
        }
        return;
    }

    // ================= compute CTAs =================
    int w    = tid >> 5;                 // warp id, handles j-pair (2w, 2w+1)
    int j0   = blockIdx.x * NJ;
    int nj   = DHID - j0; if (nj > NJ) nj = NJ;

    // ---- stage this CTA's bf16 weight slice into smem (one time) ----
    {
        int nvec = nj * 4 * (DHID / 8);            // uint4 = 8 bf16, 256 per row
        uint4* dst = (uint4*)sw;
        for (int t = tid; t < nvec; t += RTHREADS) {
            int r  = t >> 8;                        // smem row = jl*4+g
            int c  = t & 255;
            int jl = r >> 2, g = r & 3;
            const uint4* src = (const uint4*)(g_wh + ((size_t)g * DHID + j0 + jl) * DHID);
            dst[(r << 8) + c] = src[c];
        }
    }
    __syncthreads();

    int  jg0     = j0 + 2 * w;                       // first j of this warp's pair
    bool myj     = (lane < 2) && (2 * w + lane < nj);// lanes 0/1 own one j each
    bool warp_on = (2 * w < nj);
    const __nv_bfloat16* wrow0 = sw + (size_t)(2 * w)     * 4 * DHID;
    const __nv_bfloat16* wrow1 = sw + (size_t)(2 * w + 1) * 4 * DHID;
    float cst = 0.0f;                                // c state lives in lanes 0/1

#pragma unroll 1
    for (int s = 0; s < SEQ; ++s) {
        const float* hprev = g_h[s & 1];
        float*       hnext = g_h[(s + 1) & 1];

        if (warp_on) {
            // x-projection values for this lane's j (lanes 0/1 only)
            float xv0 = 0.f, xv1 = 0.f, xv2 = 0.f, xv3 = 0.f;
            if (myj) {
                const float* xp = g_xproj + (size_t)s * NPROJ + jg0 + lane;
                xv0 = __ldcg(xp);
                xv1 = __ldcg(xp + DHID);
                xv2 = __ldcg(xp + 2 * DHID);
                xv3 = __ldcg(xp + 3 * DHID);
            }

            float a00 = 0.f, a01 = 0.f, a02 = 0.f, a03 = 0.f;  // j = jg0
            float a10 = 0.f, a11 = 0.f, a12 = 0.f, a13 = 0.f;  // j = jg0+1
#pragma unroll
            for (int i = 0; i < 8; i++) {
                int k0 = (i << 8) + (lane << 3);    // 8 k per lane per iter
                float4 h0 = __ldcg((const float4*)(hprev + k0));
                float4 h1 = __ldcg((const float4*)(hprev + k0 + 4));
#define GATE(acc, base, goff)                                                 \
                {                                                             \
                    uint4 wv = *(const uint4*)((base) + (goff) + k0);         \
                    acc += BF2LO(wv.x) * h0.x + BF2HI(wv.x) * h0.y;           \
                    acc += BF2LO(wv.y) * h0.z + BF2HI(wv.y) * h0.w;           \
                    acc += BF2LO(wv.z) * h1.x + BF2HI(wv.z) * h1.y;           \
                    acc += BF2LO(wv.w) * h1.z + BF2HI(wv.w) * h1.w;           \
                }
                GATE(a00, wrow0, 0)
                GATE(a01, wrow0, DHID)
                GATE(a02, wrow0, 2 * DHID)
                GATE(a03, wrow0, 3 * DHID)
                GATE(a10, wrow1, 0)
                GATE(a11, wrow1, DHID)
                GATE(a12, wrow1, 2 * DHID)
                GATE(a13, wrow1, 3 * DHID)
#undef GATE
            }
#pragma unroll
            for (int off = 16; off; off >>= 1) {
                a00 += __shfl_xor_sync(0xffffffffu, a00, off);
                a01 += __shfl_xor_sync(0xffffffffu, a01, off);
                a02 += __shfl_xor_sync(0xffffffffu, a02, off);
                a03 += __shfl_xor_sync(0xffffffffu, a03, off);
                a10 += __shfl_xor_sync(0xffffffffu, a10, off);
                a11 += __shfl_xor_sync(0xffffffffu, a11, off);
                a12 += __shfl_xor_sync(0xffffffffu, a12, off);
                a13 += __shfl_xor_sync(0xffffffffu, a13, off);
            }
            if (myj) {
                float s0 = (lane == 0) ? a00 : a10;
                float s1 = (lane == 0) ? a01 : a11;
                float s2 = (lane == 0) ? a02 : a12;
                float s3 = (lane == 0) ? a03 : a13;
                float f  = sigm_(s0 + xv0);
                float ig = sigm_(s1 + xv1);
                float gg = tanh_(s2 + xv2);
                float oo = sigm_(s3 + xv3);
                cst = cst * f + ig * gg;
                float hn = tanh_(cst) * oo;
                __stcg(hnext + jg0 + lane, hn);
            }
        }

        if (s < SEQ - 1) {
            unsigned tgt = (unsigned)(s + 1);
            __syncthreads();                       // all warps done with step s
            if (tid == 0) {
                fence_gpu();                       // release h stores
                st_flag(&g_flag[blockIdx.x], tgt); // arrive (distributed, no contention)
                while (ld_flag(&g_epoch) < tgt) {} // wait for aggregator broadcast
                fence_gpu();                       // acquire
            }
            __syncthreads();                       // release whole CTA into s+1
        }
    }
}

// ---------------------------------------------------------------------------
// output: out[o] = b_out[o] + sum_j h_last[j] * W_out[j,o]   (h_last = g_h[0])
// ---------------------------------------------------------------------------
__global__ __launch_bounds__(256) void k_out(const float* __restrict__ Wout,
                                             const float* __restrict__ bout,
                                             float* __restrict__ out) {
    __shared__ float red[4][64];
    int ol  = threadIdx.x & 63;
    int seg = threadIdx.x >> 6;
    int o   = blockIdx.x * 64 + ol;
    const float* h = g_h[0];      // SEQ even -> final h lands in buffer 0
    float acc = 0.0f;
    int kbeg = seg * 512;
#pragma unroll 4
    for (int k = kbeg; k < kbeg + 512; ++k)
        acc += h[k] * Wout[(size_t)k * DOUT + o];
    red[seg][ol] = acc;
    __syncthreads();
    if (seg == 0)
        out[o] = bout[o] + red[0][ol] + red[1][ol] + red[2][ol] + red[3][ol];
}

// ---------------------------------------------------------------------------
extern "C" void kernel_launch(void* const* d_in, const int* in_sizes, int n_in,
                              void* d_out, int out_size) {
    const float* x = (const float*)d_in[0];
    Ptrs p;
    p.W[0] = (const float*)d_in[1]; p.b[0] = (const float*)d_in[2];   // f
    p.W[1] = (const float*)d_in[3]; p.b[1] = (const float*)d_in[4];   // i
    p.W[2] = (const float*)d_in[5]; p.b[2] = (const float*)d_in[6];   // c (g)
    p.W[3] = (const float*)d_in[7]; p.b[3] = (const float*)d_in[8];   // o
    const float* Wout = (const float*)d_in[9];
    const float* bout = (const float*)d_in[10];

    cudaFuncSetAttribute(k_rec, cudaFuncAttributeMaxDynamicSharedMemorySize, SMEM_REC);

    k_init<<<4, 1024>>>();
    k_pack<<<dim3(DHID / 32, DHID / 32, 4), dim3(32, 32)>>>(p);
    k_xproj<<<dim3(NPROJ / 128, SEQ / 128), 256>>>(x, p);
    k_rec<<<RGRID + 1, RTHREADS, SMEM_REC>>>();   // +1 aggregator CTA
    k_out<<<DOUT / 64, 256>>>(Wout, bout, (float*)d_out);
}